// round 8
// baseline (speedup 1.0000x reference)
#include <cuda_runtime.h>
#include <stdint.h>

#define SEQ    2048
#define BITS   256
#define HEADS  8
#define NBPN   12
#define MAXD   8
#define NT     1024
#define GRID_MAIN 152

// Scratch (device globals -- no allocation allowed)
__device__ uint32_t       g_tok[SEQ * 8];          // packed token bits, 32B/row
__device__ unsigned short g_AkE[SEQ * 8];          // EXPANDED ak per (row,head)
__device__ uint32_t       g_AqU[SEQ * 8];          // expand(h<<12 | aq | ar8)
__device__ uint32_t       g_tabBits[HEADS * 128];  // bit-packed table, 4KB
__device__ int            g_ArX[(MAXD + 1) * HEADS]; // expand(ar_d)^expand(ar_8)

// expand: 12-bit table index -> (wordByteOffset<<7)|(bitIndex), a pure bit
// permutation (valid because q/k/r address bits are disjoint -> + == |)
__device__ __forceinline__ uint32_t expand_idx(uint32_t x) {
    return ((x & ~31u) << 2) | (x & 31u);
}

// ---------------------------------------------------------------------------
// Precompute
// ---------------------------------------------------------------------------
__global__ void pre_kernel(const int* __restrict__ tokens,
                           const int* __restrict__ head_idx,
                           const float* __restrict__ table) {
    int tid = blockIdx.x * blockDim.x + threadIdx.x;
    int lane = tid & 31;

    if (tid < HEADS * 4096) {
        uint32_t w = __ballot_sync(0xFFFFFFFFu, table[tid] > 0.5f);
        if (lane == 0) g_tabBits[tid >> 5] = w;
    }

    if (tid < (MAXD + 1) * HEADS) {
        int d = tid / HEADS, h = tid % HEADS;
        uint32_t ard = 0, ar8 = 0;
        for (int k = 0; k < NBPN; k++) {
            int idx = head_idx[h * NBPN + k];
            if (idx >= 2 * BITS) {
                int p = idx - 2 * BITS;
                if (p > 3) p = 3;
                ard |= (uint32_t)((d    >> p) & 1) << k;
                ar8 |= (uint32_t)((MAXD >> p) & 1) << k;
            }
        }
        g_ArX[tid] = (int)(expand_idx(ard) ^ expand_idx(ar8));
    }

    int row = tid >> 5;
    if (row < SEQ) {
        uint32_t w[8];
        #pragma unroll
        for (int q = 0; q < 8; q++) {
            int v = tokens[row * BITS + q * 32 + lane];
            w[q] = __ballot_sync(0xFFFFFFFFu, v & 1);
        }
        if (lane < 8) {
            g_tok[row * 8 + lane] = w[lane];
            int h = lane;
            uint32_t aq = 0, ak = 0, ar8 = 0;
            for (int k = 0; k < NBPN; k++) {
                int idx = head_idx[h * NBPN + k];
                if (idx < BITS) {
                    aq |= ((w[idx >> 5] >> (idx & 31)) & 1u) << k;
                } else if (idx < 2 * BITS) {
                    int i2 = idx - BITS;
                    ak |= ((w[i2 >> 5] >> (i2 & 31)) & 1u) << k;
                } else {
                    int p = idx - 2 * BITS;
                    if (p > 3) p = 3;
                    ar8 |= (uint32_t)((MAXD >> p) & 1) << k;
                }
            }
            g_AkE[row * 8 + h] = (unsigned short)expand_idx(ak);
            g_AqU[row * 8 + h] = expand_idx(((uint32_t)h << 12) | aq | ar8);
        }
    }
}

// ---------------------------------------------------------------------------
// Main: persistent CTAs. A QUAD (4 warps) processes a row DUO (2d, 2d+1)
// with j-stride 128; akv/token loads shared by both rows. Bank-private
// replicated bit-table; additive expanded addressing (IMAD/IADD3 mix).
// ---------------------------------------------------------------------------
__global__ __launch_bounds__(NT, 1)
void main_kernel(float* __restrict__ out) {
    extern __shared__ unsigned char smem[];
    // sRep at offset 0: word w, replica L at byte w*128 + L*4
    uint4*    sAk4   = (uint4*)(smem + 131072);           // 32768 B (expanded Ak)
    uint4*    sTokLo = (uint4*)(smem + 163840);           // 32768 B
    uint4*    sTokHi = (uint4*)(smem + 196608);           // 32768 B
    int*      sArX   = (int*)(smem + 229376);             // 72 ints
    uint32_t* sRed   = (uint32_t*)(smem + 229664);        // 32 warps x 18

    const int tid = threadIdx.x;
    const int lane = tid & 31, wid = tid >> 5;

    // Stage working set
    {
        uint32_t val = g_tabBits[tid];
        uint32_t* sRep = (uint32_t*)smem;
        #pragma unroll
        for (int r = 0; r < 32; r++) {
            int L = (r + lane) & 31;                 // staggered, conflict-free
            sRep[tid * 32 + L] = val;
        }
        const uint4* g2 = (const uint4*)g_AkE;
        for (int x = tid; x < 2048; x += NT) sAk4[x] = g2[x];
        const uint4* g3 = (const uint4*)g_tok;
        for (int x = tid; x < 4096; x += NT) {
            uint4 v = g3[x];
            if (x & 1) sTokHi[x >> 1] = v; else sTokLo[x >> 1] = v;
        }
        if (tid < (MAXD + 1) * HEADS) sArX[tid] = g_ArX[tid];
    }
    __syncthreads();

    const int quad = wid & 7, sub = wid >> 3;   // quad members share an SMSP set
    const int bx = (int)blockIdx.x;
    const int d = quad * GRID_MAIN + ((quad & 1) ? (GRID_MAIN - 1 - bx) : bx);
    const bool active = (d < SEQ / 2);
    const int i1 = 2 * d, i2 = 2 * d + 1;

    uint32_t a1[8] = {0,0,0,0,0,0,0,0};
    uint32_t a2[8] = {0,0,0,0,0,0,0,0};
    int kmax1 = -1, kmax2 = -1;
    const uint32_t laneOff = (uint32_t)lane << 2;

    if (active) {
        uint32_t u1[8], u2[8];
        {
            const uint4* gu = (const uint4*)(g_AqU + i1 * 8);
            uint4 x0 = gu[0], x1 = gu[1], x2 = gu[2], x3 = gu[3];
            u1[0]=x0.x; u1[1]=x0.y; u1[2]=x0.z; u1[3]=x0.w;
            u1[4]=x1.x; u1[5]=x1.y; u1[6]=x1.z; u1[7]=x1.w;
            u2[0]=x2.x; u2[1]=x2.y; u2[2]=x2.z; u2[3]=x2.w;
            u2[4]=x3.x; u2[5]=x3.y; u2[6]=x3.z; u2[7]=x3.w;
        }

        // main loop: j+8 <= i1 (valid for both rows; rel part is ar8)
        for (int j = lane + 32 * sub; j + MAXD <= i1; j += 128) {
            uint4 akv = sAk4[j];
            uint32_t k0 = akv.x & 0xFFFFu, k1 = akv.x >> 16;
            uint32_t k2 = akv.y & 0xFFFFu, k3 = akv.y >> 16;
            uint32_t k4 = akv.z & 0xFFFFu, k5 = akv.z >> 16;
            uint32_t k6 = akv.w & 0xFFFFu, k7 = akv.w >> 16;

            int v1 = 0, v2 = 0;
            {
                uint32_t A, w;
                A = u1[0] + k0; w = *(const uint32_t*)(smem + ((A & 0xFFFFFF80u) | laneOff)); v1 += (int)((w >> (A & 31u)) & 1u);
                A = u2[0] + k0; w = *(const uint32_t*)(smem + ((A & 0xFFFFFF80u) | laneOff)); v2 += (int)((w >> (A & 31u)) & 1u);
                A = u1[1] + k1; w = *(const uint32_t*)(smem + ((A & 0xFFFFFF80u) | laneOff)); v1 += (int)((w >> (A & 31u)) & 1u);
                A = u2[1] + k1; w = *(const uint32_t*)(smem + ((A & 0xFFFFFF80u) | laneOff)); v2 += (int)((w >> (A & 31u)) & 1u);
                A = u1[2] + k2; w = *(const uint32_t*)(smem + ((A & 0xFFFFFF80u) | laneOff)); v1 += (int)((w >> (A & 31u)) & 1u);
                A = u2[2] + k2; w = *(const uint32_t*)(smem + ((A & 0xFFFFFF80u) | laneOff)); v2 += (int)((w >> (A & 31u)) & 1u);
                A = u1[3] + k3; w = *(const uint32_t*)(smem + ((A & 0xFFFFFF80u) | laneOff)); v1 += (int)((w >> (A & 31u)) & 1u);
                A = u2[3] + k3; w = *(const uint32_t*)(smem + ((A & 0xFFFFFF80u) | laneOff)); v2 += (int)((w >> (A & 31u)) & 1u);
                A = u1[4] + k4; w = *(const uint32_t*)(smem + ((A & 0xFFFFFF80u) | laneOff)); v1 += (int)((w >> (A & 31u)) & 1u);
                A = u2[4] + k4; w = *(const uint32_t*)(smem + ((A & 0xFFFFFF80u) | laneOff)); v2 += (int)((w >> (A & 31u)) & 1u);
                A = u1[5] + k5; w = *(const uint32_t*)(smem + ((A & 0xFFFFFF80u) | laneOff)); v1 += (int)((w >> (A & 31u)) & 1u);
                A = u2[5] + k5; w = *(const uint32_t*)(smem + ((A & 0xFFFFFF80u) | laneOff)); v2 += (int)((w >> (A & 31u)) & 1u);
                A = u1[6] + k6; w = *(const uint32_t*)(smem + ((A & 0xFFFFFF80u) | laneOff)); v1 += (int)((w >> (A & 31u)) & 1u);
                A = u2[6] + k6; w = *(const uint32_t*)(smem + ((A & 0xFFFFFF80u) | laneOff)); v2 += (int)((w >> (A & 31u)) & 1u);
                A = u1[7] + k7; w = *(const uint32_t*)(smem + ((A & 0xFFFFFF80u) | laneOff)); v1 += (int)((w >> (A & 31u)) & 1u);
                A = u2[7] + k7; w = *(const uint32_t*)(smem + ((A & 0xFFFFFF80u) | laneOff)); v2 += (int)((w >> (A & 31u)) & 1u);
            }

            uint32_t m1 = (v1 >= HEADS / 2) ? 0xFFFFFFFFu : 0u;
            uint32_t m2 = (v2 >= HEADS / 2) ? 0xFFFFFFFFu : 0u;
            uint4 t0 = sTokLo[j];
            uint4 t1 = sTokHi[j];
            a1[0] ^= t0.x & m1; a1[1] ^= t0.y & m1; a1[2] ^= t0.z & m1; a1[3] ^= t0.w & m1;
            a1[4] ^= t1.x & m1; a1[5] ^= t1.y & m1; a1[6] ^= t1.z & m1; a1[7] ^= t1.w & m1;
            a2[0] ^= t0.x & m2; a2[1] ^= t0.y & m2; a2[2] ^= t0.z & m2; a2[3] ^= t0.w & m2;
            a2[4] ^= t1.x & m2; a2[5] ^= t1.y & m2; a2[6] ^= t1.z & m2; a2[7] ^= t1.w & m2;

            kmax1 = max(kmax1, (v1 << 12) | (2047 - j));
            kmax2 = max(kmax2, (v2 << 12) | (2047 - j));
        }

        // diagonal tail (sub 0 warp): lanes 0-7 -> row i1 dist 0..7,
        // lanes 8-16 -> row i2 dist 0..8 (dist 8 delta = 0)
        if (sub == 0 && lane < 17) {
            int row1 = (lane < 8);
            int dist = row1 ? lane : (lane - 8);
            int base = row1 ? i1 : i2;
            bool ok = dist <= base;
            if (ok) {
                int jt = base - dist;
                const unsigned short* s = (const unsigned short*)sAk4 + jt * 8;
                const int* ax = sArX + dist * 8;
                int v = 0;
                #pragma unroll
                for (int h = 0; h < 8; h++) {
                    uint32_t uh = row1 ? u1[h] : u2[h];
                    uint32_t A = (uh ^ (uint32_t)ax[h]) + (uint32_t)s[h];
                    uint32_t w = *(const uint32_t*)(smem + ((A & 0xFFFFFF80u) | laneOff));
                    v += (int)((w >> (A & 31u)) & 1u);
                }
                uint32_t um = (v >= HEADS / 2) ? 0xFFFFFFFFu : 0u;
                uint32_t m1 = row1 ? um : 0u;
                uint32_t m2 = row1 ? 0u : um;
                uint4 t0 = sTokLo[jt];
                uint4 t1 = sTokHi[jt];
                a1[0] ^= t0.x & m1; a1[1] ^= t0.y & m1; a1[2] ^= t0.z & m1; a1[3] ^= t0.w & m1;
                a1[4] ^= t1.x & m1; a1[5] ^= t1.y & m1; a1[6] ^= t1.z & m1; a1[7] ^= t1.w & m1;
                a2[0] ^= t0.x & m2; a2[1] ^= t0.y & m2; a2[2] ^= t0.z & m2; a2[3] ^= t0.w & m2;
                a2[4] ^= t1.x & m2; a2[5] ^= t1.y & m2; a2[6] ^= t1.z & m2; a2[7] ^= t1.w & m2;
                int key = (v << 12) | (2047 - jt);
                if (row1) kmax1 = max(kmax1, key); else kmax2 = max(kmax2, key);
            }
        }

        // warp butterfly
        #pragma unroll
        for (int s = 16; s; s >>= 1) {
            #pragma unroll
            for (int q = 0; q < 8; q++) {
                a1[q] ^= __shfl_xor_sync(0xFFFFFFFFu, a1[q], s);
                a2[q] ^= __shfl_xor_sync(0xFFFFFFFFu, a2[q], s);
            }
            kmax1 = max(kmax1, __shfl_xor_sync(0xFFFFFFFFu, kmax1, s));
            kmax2 = max(kmax2, __shfl_xor_sync(0xFFFFFFFFu, kmax2, s));
        }

        // subs 1-3 park partials for sub 0
        if (sub != 0 && lane < 18) {
            uint32_t v = a1[0];
            if (lane == 1) v = a1[1];
            if (lane == 2) v = a1[2];
            if (lane == 3) v = a1[3];
            if (lane == 4) v = a1[4];
            if (lane == 5) v = a1[5];
            if (lane == 6) v = a1[6];
            if (lane == 7) v = a1[7];
            if (lane == 8)  v = a2[0];
            if (lane == 9)  v = a2[1];
            if (lane == 10) v = a2[2];
            if (lane == 11) v = a2[3];
            if (lane == 12) v = a2[4];
            if (lane == 13) v = a2[5];
            if (lane == 14) v = a2[6];
            if (lane == 15) v = a2[7];
            if (lane == 16) v = (uint32_t)kmax1;
            if (lane == 17) v = (uint32_t)kmax2;
            sRed[wid * 18 + lane] = v;
        }
    }

    __syncthreads();   // single block sync

    if (active && sub == 0) {
        #pragma unroll
        for (int s = 1; s < 4; s++) {
            const uint32_t* p = sRed + (wid + 8 * s) * 18;
            #pragma unroll
            for (int q = 0; q < 8; q++) { a1[q] ^= p[q]; a2[q] ^= p[8 + q]; }
            kmax1 = max(kmax1, (int)p[16]);
            kmax2 = max(kmax2, (int)p[17]);
        }

        const uint32_t* lo = (const uint32_t*)sTokLo;
        const uint32_t* hi = (const uint32_t*)sTokHi;
        int widx = lane >> 2;
        int sh = (lane & 3) * 8;

        #pragma unroll
        for (int r = 0; r < 2; r++) {
            const uint32_t* a = r ? a2 : a1;
            int km = r ? kmax2 : kmax1;
            int row = r ? i2 : i1;
            uint32_t w;
            if ((km >> 12) >= HEADS / 2) {
                w = a[0];
                if (widx == 1) w = a[1];
                if (widx == 2) w = a[2];
                if (widx == 3) w = a[3];
                if (widx == 4) w = a[4];
                if (widx == 5) w = a[5];
                if (widx == 6) w = a[6];
                if (widx == 7) w = a[7];
            } else {
                int aj = 2047 - (km & 4095);
                w = (widx < 4) ? lo[aj * 4 + widx] : hi[aj * 4 + (widx - 4)];
            }
            float4* o = (float4*)(out + row * BITS + lane * 8);
            o[0] = make_float4((float)((w >> (sh + 0)) & 1u), (float)((w >> (sh + 1)) & 1u),
                               (float)((w >> (sh + 2)) & 1u), (float)((w >> (sh + 3)) & 1u));
            o[1] = make_float4((float)((w >> (sh + 4)) & 1u), (float)((w >> (sh + 5)) & 1u),
                               (float)((w >> (sh + 6)) & 1u), (float)((w >> (sh + 7)) & 1u));
        }
    }
}

extern "C" void kernel_launch(void* const* d_in, const int* in_sizes, int n_in,
                              void* d_out, int out_size) {
    const int*   tokens   = (const int*)d_in[0];
    const int*   head_idx = (const int*)d_in[1];
    const float* table    = (const float*)d_in[2];
    float*       out      = (float*)d_out;

    const int SMEM_BYTES = 229664 + 32 * 18 * 4;   // 231968 B
    cudaFuncSetAttribute(main_kernel,
                         cudaFuncAttributeMaxDynamicSharedMemorySize, SMEM_BYTES);

    pre_kernel<<<(SEQ * 32 + 255) / 256, 256>>>(tokens, head_idx, table);
    main_kernel<<<GRID_MAIN, NT, SMEM_BYTES>>>(out);
}

// round 9
// speedup vs baseline: 1.1098x; 1.1098x over previous
#include <cuda_runtime.h>
#include <stdint.h>

#define SEQ    2048
#define BITS   256
#define HEADS  8
#define NBPN   12
#define MAXD   8
#define NT     1024
#define GRID_MAIN 152

// Scratch (device globals -- no allocation allowed)
__device__ uint32_t       g_tok[SEQ * 8];          // packed token bits, 32B/row
__device__ unsigned short g_AkE[SEQ * 8];          // EXPANDED ak per (row,head)
__device__ uint32_t       g_AqU[SEQ * 8];          // expand(h<<12 | aq | ar8)
__device__ uint32_t       g_tabBits[HEADS * 128];  // bit-packed table, 4KB
__device__ int            g_ArX[(MAXD + 1) * HEADS]; // expand(ar_d)^expand(ar_8)

// expand: 12-bit table index -> (wordByteOffset<<7)|(bitIndex), a pure bit
// permutation (valid because q/k/r address bits are disjoint -> + == |)
__device__ __forceinline__ uint32_t expand_idx(uint32_t x) {
    return ((x & ~31u) << 2) | (x & 31u);
}

// ---------------------------------------------------------------------------
// Precompute
// ---------------------------------------------------------------------------
__global__ void pre_kernel(const int* __restrict__ tokens,
                           const int* __restrict__ head_idx,
                           const float* __restrict__ table) {
    int tid = blockIdx.x * blockDim.x + threadIdx.x;
    int lane = tid & 31;

    if (tid < HEADS * 4096) {
        uint32_t w = __ballot_sync(0xFFFFFFFFu, table[tid] > 0.5f);
        if (lane == 0) g_tabBits[tid >> 5] = w;
    }

    if (tid < (MAXD + 1) * HEADS) {
        int d = tid / HEADS, h = tid % HEADS;
        uint32_t ard = 0, ar8 = 0;
        for (int k = 0; k < NBPN; k++) {
            int idx = head_idx[h * NBPN + k];
            if (idx >= 2 * BITS) {
                int p = idx - 2 * BITS;
                if (p > 3) p = 3;
                ard |= (uint32_t)((d    >> p) & 1) << k;
                ar8 |= (uint32_t)((MAXD >> p) & 1) << k;
            }
        }
        g_ArX[tid] = (int)(expand_idx(ard) ^ expand_idx(ar8));
    }

    int row = tid >> 5;
    if (row < SEQ) {
        uint32_t w[8];
        #pragma unroll
        for (int q = 0; q < 8; q++) {
            int v = tokens[row * BITS + q * 32 + lane];
            w[q] = __ballot_sync(0xFFFFFFFFu, v & 1);
        }
        if (lane < 8) {
            g_tok[row * 8 + lane] = w[lane];
            int h = lane;
            uint32_t aq = 0, ak = 0, ar8 = 0;
            for (int k = 0; k < NBPN; k++) {
                int idx = head_idx[h * NBPN + k];
                if (idx < BITS) {
                    aq |= ((w[idx >> 5] >> (idx & 31)) & 1u) << k;
                } else if (idx < 2 * BITS) {
                    int i2 = idx - BITS;
                    ak |= ((w[i2 >> 5] >> (i2 & 31)) & 1u) << k;
                } else {
                    int p = idx - 2 * BITS;
                    if (p > 3) p = 3;
                    ar8 |= (uint32_t)((MAXD >> p) & 1) << k;
                }
            }
            g_AkE[row * 8 + h] = (unsigned short)expand_idx(ak);
            g_AqU[row * 8 + h] = expand_idx(((uint32_t)h << 12) | aq | ar8);
        }
    }
}

// ---------------------------------------------------------------------------
// Main: persistent CTAs, TWO WARPS PER ROW, bank-private replicated bit-table,
// additive expanded addressing (IMAD/IADD3 pipe mix), diagonal peeled to an
// 8-lane tail, divergent token XOR.
// ---------------------------------------------------------------------------
__global__ __launch_bounds__(NT, 1)
void main_kernel(float* __restrict__ out) {
    extern __shared__ unsigned char smem[];
    // sRep at offset 0: word w, replica L at byte w*128 + L*4
    uint4*    sAk4   = (uint4*)(smem + 131072);           // 32768 B (expanded Ak)
    uint4*    sTokLo = (uint4*)(smem + 163840);           // 32768 B
    uint4*    sTokHi = (uint4*)(smem + 196608);           // 32768 B
    int*      sArX   = (int*)(smem + 229376);             // 72 ints
    uint32_t* sRed   = (uint32_t*)(smem + 229664);        // 32 warps x 9

    const int tid = threadIdx.x;
    const int lane = tid & 31, wid = tid >> 5;

    // Stage working set
    {
        uint32_t val = g_tabBits[tid];
        uint32_t* sRep = (uint32_t*)smem;
        #pragma unroll
        for (int r = 0; r < 32; r++) {
            int L = (r + lane) & 31;                 // staggered, conflict-free
            sRep[tid * 32 + L] = val;
        }
        const uint4* g2 = (const uint4*)g_AkE;
        for (int x = tid; x < 2048; x += NT) sAk4[x] = g2[x];
        const uint4* g3 = (const uint4*)g_tok;
        for (int x = tid; x < 4096; x += NT) {
            uint4 v = g3[x];
            if (x & 1) sTokHi[x >> 1] = v; else sTokLo[x >> 1] = v;
        }
        if (tid < (MAXD + 1) * HEADS) sArX[tid] = g_ArX[tid];
    }
    __syncthreads();

    const int pair = wid >> 1, sub = wid & 1;
    const int bx = (int)blockIdx.x;
    const int i = pair * GRID_MAIN + ((pair & 1) ? (GRID_MAIN - 1 - bx) : bx);
    const bool active = (i < SEQ);

    uint32_t a[8] = {0, 0, 0, 0, 0, 0, 0, 0};
    int kmax = -1;
    const uint32_t laneOff = (uint32_t)lane << 2;

    if (active) {
        uint32_t u[8];
        {
            const uint4* gu = (const uint4*)(g_AqU + i * 8);
            uint4 u03 = gu[0], u47 = gu[1];
            u[0] = u03.x; u[1] = u03.y; u[2] = u03.z; u[3] = u03.w;
            u[4] = u47.x; u[5] = u47.y; u[6] = u47.z; u[7] = u47.w;
        }

        // main loop: j <= i-8 (rel part is exactly ar8 here; no fixups)
        #pragma unroll 2
        for (int j = lane + 32 * sub; j + MAXD <= i; j += 64) {
            uint4 akv = sAk4[j];
            uint32_t A0 = u[0] + (akv.x & 0xFFFFu);
            uint32_t A1 = u[1] + (akv.x >> 16);
            uint32_t A2 = u[2] + (akv.y & 0xFFFFu);
            uint32_t A3 = u[3] + (akv.y >> 16);
            uint32_t A4 = u[4] + (akv.z & 0xFFFFu);
            uint32_t A5 = u[5] + (akv.z >> 16);
            uint32_t A6 = u[6] + (akv.w & 0xFFFFu);
            uint32_t A7 = u[7] + (akv.w >> 16);

            uint32_t w0 = *(const uint32_t*)(smem + ((A0 & 0xFFFFFF80u) | laneOff));
            uint32_t w1 = *(const uint32_t*)(smem + ((A1 & 0xFFFFFF80u) | laneOff));
            uint32_t w2 = *(const uint32_t*)(smem + ((A2 & 0xFFFFFF80u) | laneOff));
            uint32_t w3 = *(const uint32_t*)(smem + ((A3 & 0xFFFFFF80u) | laneOff));
            uint32_t w4 = *(const uint32_t*)(smem + ((A4 & 0xFFFFFF80u) | laneOff));
            uint32_t w5 = *(const uint32_t*)(smem + ((A5 & 0xFFFFFF80u) | laneOff));
            uint32_t w6 = *(const uint32_t*)(smem + ((A6 & 0xFFFFFF80u) | laneOff));
            uint32_t w7 = *(const uint32_t*)(smem + ((A7 & 0xFFFFFF80u) | laneOff));

            int v = (int)((w0 >> (A0 & 31u)) & 1u) + (int)((w1 >> (A1 & 31u)) & 1u)
                  + (int)((w2 >> (A2 & 31u)) & 1u) + (int)((w3 >> (A3 & 31u)) & 1u)
                  + (int)((w4 >> (A4 & 31u)) & 1u) + (int)((w5 >> (A5 & 31u)) & 1u)
                  + (int)((w6 >> (A6 & 31u)) & 1u) + (int)((w7 >> (A7 & 31u)) & 1u);

            if (v >= HEADS / 2) {      // divergent but cheap: plain XOR path
                uint4 t0 = sTokLo[j];
                uint4 t1 = sTokHi[j];
                a[0] ^= t0.x; a[1] ^= t0.y; a[2] ^= t0.z; a[3] ^= t0.w;
                a[4] ^= t1.x; a[5] ^= t1.y; a[6] ^= t1.z; a[7] ^= t1.w;
            }
            kmax = max(kmax, (v << 12) | (2047 - j));
        }

        // diagonal tail: d = 0..7, lane d handles j = i-d (sub 0 warp only)
        if (sub == 0 && lane < MAXD && lane <= i) {
            int jt = i - lane;
            const unsigned short* s = (const unsigned short*)sAk4 + jt * 8;
            const int* ax = sArX + lane * 8;
            int v = 0;
            #pragma unroll
            for (int h = 0; h < 8; h++) {
                uint32_t A = (u[h] ^ (uint32_t)ax[h]) + (uint32_t)s[h];
                uint32_t w = *(const uint32_t*)(smem + ((A & 0xFFFFFF80u) | laneOff));
                v += (int)((w >> (A & 31u)) & 1u);
            }
            if (v >= HEADS / 2) {
                uint4 t0 = sTokLo[jt];
                uint4 t1 = sTokHi[jt];
                a[0] ^= t0.x; a[1] ^= t0.y; a[2] ^= t0.z; a[3] ^= t0.w;
                a[4] ^= t1.x; a[5] ^= t1.y; a[6] ^= t1.z; a[7] ^= t1.w;
            }
            kmax = max(kmax, (v << 12) | (2047 - jt));
        }

        // warp butterfly
        #pragma unroll
        for (int s = 16; s; s >>= 1) {
            #pragma unroll
            for (int q = 0; q < 8; q++)
                a[q] ^= __shfl_xor_sync(0xFFFFFFFFu, a[q], s);
            kmax = max(kmax, __shfl_xor_sync(0xFFFFFFFFu, kmax, s));
        }

        // odd warp parks its partial for its even partner
        if (sub == 1 && lane < 9) {
            uint32_t v = (lane < 8) ? a[lane] : (uint32_t)kmax;
            sRed[wid * 9 + lane] = v;
        }
    }

    __syncthreads();   // single block sync

    if (active && sub == 0) {
        const uint32_t* p = sRed + (wid + 1) * 9;
        #pragma unroll
        for (int q = 0; q < 8; q++) a[q] ^= p[q];
        kmax = max(kmax, (int)p[8]);

        int widx = lane >> 2;
        uint32_t w;
        if ((kmax >> 12) >= HEADS / 2) {          // any attended -> parity
            w = a[0];
            if (widx == 1) w = a[1];
            if (widx == 2) w = a[2];
            if (widx == 3) w = a[3];
            if (widx == 4) w = a[4];
            if (widx == 5) w = a[5];
            if (widx == 6) w = a[6];
            if (widx == 7) w = a[7];
        } else {                                   // fallback: argmax row
            int aj = 2047 - (kmax & 4095);
            const uint32_t* lo = (const uint32_t*)sTokLo;
            const uint32_t* hi = (const uint32_t*)sTokHi;
            w = (widx < 4) ? lo[aj * 4 + widx] : hi[aj * 4 + (widx - 4)];
        }
        int sh = (lane & 3) * 8;
        float4* o = (float4*)(out + i * BITS + lane * 8);
        o[0] = make_float4((float)((w >> (sh + 0)) & 1u), (float)((w >> (sh + 1)) & 1u),
                           (float)((w >> (sh + 2)) & 1u), (float)((w >> (sh + 3)) & 1u));
        o[1] = make_float4((float)((w >> (sh + 4)) & 1u), (float)((w >> (sh + 5)) & 1u),
                           (float)((w >> (sh + 6)) & 1u), (float)((w >> (sh + 7)) & 1u));
    }
}

extern "C" void kernel_launch(void* const* d_in, const int* in_sizes, int n_in,
                              void* d_out, int out_size) {
    const int*   tokens   = (const int*)d_in[0];
    const int*   head_idx = (const int*)d_in[1];
    const float* table    = (const float*)d_in[2];
    float*       out      = (float*)d_out;

    const int SMEM_BYTES = 229664 + 32 * 9 * 4;   // 230816 B
    cudaFuncSetAttribute(main_kernel,
                         cudaFuncAttributeMaxDynamicSharedMemorySize, SMEM_BYTES);

    pre_kernel<<<(SEQ * 32 + 255) / 256, 256>>>(tokens, head_idx, table);
    main_kernel<<<GRID_MAIN, NT, SMEM_BYTES>>>(out);
}